// round 1
// baseline (speedup 1.0000x reference)
#include <cuda_runtime.h>
#include <cstdint>

// Problem shape (fixed by the reference setup_inputs)
#define B_SZ   4
#define N_PTS  8192
#define M_PTS  8192

// Compute-kernel tiling
#define IPT      4                 // owner points per thread per direction
#define BLOCK    256               // threads per block
#define OWNERS   (IPT * BLOCK)     // 1024 owner points per block
#define S_CHUNKS 16                // split of the scanned dimension
#define CHUNK    (M_PTS / S_CHUNKS)// 512 scanned points per block
#define TILE     256               // shared-memory tile (== BLOCK)

__device__ float gMinX[B_SZ * N_PTS];   // min over target of (0.5|t|^2 - p.t), per pred point
__device__ float gMinY[B_SZ * M_PTS];   // min over pred   of (0.5|p|^2 - t.p), per target point
__device__ float gSumX;
__device__ float gSumY;

__device__ __forceinline__ void atomicMinFloat(float* addr, float val) {
    // Sign-correct float atomic-min (values may be negative).
    if (val >= 0.0f) {
        atomicMin((int*)addr, __float_as_int(val));
    } else {
        atomicMax((unsigned int*)addr, __float_as_uint(val));
    }
}

__global__ void init_kernel() {
    int i = blockIdx.x * blockDim.x + threadIdx.x;
    if (i < B_SZ * N_PTS) gMinX[i] = __int_as_float(0x7f800000); // +inf
    if (i < B_SZ * M_PTS) gMinY[i] = __int_as_float(0x7f800000);
    if (i == 0) { gSumX = 0.0f; gSumY = 0.0f; }
}

__global__ __launch_bounds__(BLOCK) void chamfer_kernel(
    const float* __restrict__ pred, const float* __restrict__ target)
{
    __shared__ float4 sT[TILE];   // target tile: x,y,z, 0.5*|.|^2
    __shared__ float4 sP[TILE];   // pred   tile: x,y,z, 0.5*|.|^2

    const int b = blockIdx.z;
    const float* __restrict__ predB = pred   + (size_t)b * N_PTS * 3;
    const float* __restrict__ targB = target + (size_t)b * M_PTS * 3;

    const int ownerBase = blockIdx.x * OWNERS;
    const int chunkBase = blockIdx.y * CHUNK;
    const int t = threadIdx.x;

    float ax[IPT], ay[IPT], az[IPT];   // owned pred points
    float cx[IPT], cy[IPT], cz[IPT];   // owned target points
    float mn1[IPT], mn2[IPT];

#pragma unroll
    for (int p = 0; p < IPT; p++) {
        int i = ownerBase + t + p * BLOCK;
        ax[p] = predB[3 * i + 0];
        ay[p] = predB[3 * i + 1];
        az[p] = predB[3 * i + 2];
        cx[p] = targB[3 * i + 0];
        cy[p] = targB[3 * i + 1];
        cz[p] = targB[3 * i + 2];
        mn1[p] = __int_as_float(0x7f800000);
        mn2[p] = __int_as_float(0x7f800000);
    }

    for (int tile = 0; tile < CHUNK; tile += TILE) {
        int j = chunkBase + tile + t;   // t < TILE
        {
            float x = targB[3 * j + 0], y = targB[3 * j + 1], z = targB[3 * j + 2];
            sT[t] = make_float4(x, y, z, 0.5f * (x * x + y * y + z * z));
            x = predB[3 * j + 0]; y = predB[3 * j + 1]; z = predB[3 * j + 2];
            sP[t] = make_float4(x, y, z, 0.5f * (x * x + y * y + z * z));
        }
        __syncthreads();

#pragma unroll 4
        for (int jj = 0; jj < TILE; jj++) {
            float4 bb = sT[jj];
#pragma unroll
            for (int p = 0; p < IPT; p++) {
                float v = fmaf(-ax[p], bb.x, bb.w);
                v = fmaf(-ay[p], bb.y, v);
                v = fmaf(-az[p], bb.z, v);
                mn1[p] = fminf(mn1[p], v);
            }
            float4 qq = sP[jj];
#pragma unroll
            for (int p = 0; p < IPT; p++) {
                float v = fmaf(-cx[p], qq.x, qq.w);
                v = fmaf(-cy[p], qq.y, v);
                v = fmaf(-cz[p], qq.z, v);
                mn2[p] = fminf(mn2[p], v);
            }
        }
        __syncthreads();
    }

#pragma unroll
    for (int p = 0; p < IPT; p++) {
        int i = ownerBase + t + p * BLOCK;
        atomicMinFloat(&gMinX[b * N_PTS + i], mn1[p]);
        atomicMinFloat(&gMinY[b * M_PTS + i], mn2[p]);
    }
}

__global__ void reduce_kernel(const float* __restrict__ pred,
                              const float* __restrict__ target)
{
    __shared__ float sx[256 / 32];
    __shared__ float sy[256 / 32];

    int i = blockIdx.x * blockDim.x + threadIdx.x;
    float vx = 0.0f, vy = 0.0f;
    if (i < B_SZ * N_PTS) {
        float x = pred[3 * i + 0], y = pred[3 * i + 1], z = pred[3 * i + 2];
        vx = 2.0f * gMinX[i] + (x * x + y * y + z * z);
    }
    if (i < B_SZ * M_PTS) {
        float x = target[3 * i + 0], y = target[3 * i + 1], z = target[3 * i + 2];
        vy = 2.0f * gMinY[i] + (x * x + y * y + z * z);
    }
    // warp reduce
#pragma unroll
    for (int off = 16; off > 0; off >>= 1) {
        vx += __shfl_down_sync(0xffffffffu, vx, off);
        vy += __shfl_down_sync(0xffffffffu, vy, off);
    }
    int lane = threadIdx.x & 31;
    int warp = threadIdx.x >> 5;
    if (lane == 0) { sx[warp] = vx; sy[warp] = vy; }
    __syncthreads();
    if (warp == 0) {
        vx = (lane < (blockDim.x >> 5)) ? sx[lane] : 0.0f;
        vy = (lane < (blockDim.x >> 5)) ? sy[lane] : 0.0f;
#pragma unroll
        for (int off = 16; off > 0; off >>= 1) {
            vx += __shfl_down_sync(0xffffffffu, vx, off);
            vy += __shfl_down_sync(0xffffffffu, vy, off);
        }
        if (lane == 0) {
            atomicAdd(&gSumX, vx);
            atomicAdd(&gSumY, vy);
        }
    }
}

__global__ void finalize_kernel(const float* __restrict__ bpp,
                                const float* __restrict__ lamda,
                                float* __restrict__ out)
{
    float dist = gSumX * (1.0f / (B_SZ * N_PTS)) + gSumY * (1.0f / (B_SZ * M_PTS));
    out[0] = dist + lamda[0] * bpp[0];
}

extern "C" void kernel_launch(void* const* d_in, const int* in_sizes, int n_in,
                              void* d_out, int out_size)
{
    const float* pred   = (const float*)d_in[0];
    const float* target = (const float*)d_in[1];
    const float* bpp    = (const float*)d_in[2];
    const float* lamda  = (const float*)d_in[3];
    float* out = (float*)d_out;

    // 1) init mins / accumulators
    init_kernel<<<(B_SZ * N_PTS + 255) / 256, 256>>>();

    // 2) fused two-direction chamfer min
    dim3 grid(N_PTS / OWNERS, S_CHUNKS, B_SZ);  // (8, 16, 4)
    chamfer_kernel<<<grid, BLOCK>>>(pred, target);

    // 3) per-point d2 + sum reduction
    reduce_kernel<<<(B_SZ * N_PTS + 255) / 256, 256>>>(pred, target);

    // 4) scalar finalize
    finalize_kernel<<<1, 1>>>(bpp, lamda, out);
}

// round 2
// speedup vs baseline: 1.1469x; 1.1469x over previous
#include <cuda_runtime.h>
#include <cstdint>

// Problem shape (fixed by the reference setup_inputs)
#define B_SZ   4
#define N_PTS  8192
#define M_PTS  8192

// Compute-kernel tiling
#define IPT      4                 // owner points per thread per direction
#define BLOCK    256               // threads per block
#define OWNERS   (IPT * BLOCK)     // 1024 owner points per block
#define S_CHUNKS 16                // split of the scanned dimension
#define CHUNK    (M_PTS / S_CHUNKS)// 512 scanned points per block
#define TILE     256               // shared-memory tile (== BLOCK)
#define TILE2    (TILE / 2)

typedef unsigned long long ull;

__device__ float gMinX[B_SZ * N_PTS];   // min over target of (0.5|t|^2 - p.t), per pred point
__device__ float gMinY[B_SZ * M_PTS];   // min over pred   of (0.5|p|^2 - t.p), per target point
__device__ float gSumX;
__device__ float gSumY;

// ---- packed f32x2 helpers (FFMA2 path; not emitted by ptxas from C++) ----
__device__ __forceinline__ ull pack2(float lo, float hi) {
    ull r;
    asm("mov.b64 %0, {%1,%2};" : "=l"(r) : "f"(lo), "f"(hi));
    return r;
}
__device__ __forceinline__ ull fma2(ull a, ull b, ull c) {
    ull d;
    asm("fma.rn.f32x2 %0, %1, %2, %3;" : "=l"(d) : "l"(a), "l"(b), "l"(c));
    return d;
}
__device__ __forceinline__ void unpack2(ull v, float& lo, float& hi) {
    asm("mov.b64 {%0,%1}, %2;" : "=f"(lo), "=f"(hi) : "l"(v));
}

__device__ __forceinline__ void atomicMinFloat(float* addr, float val) {
    // Sign-correct float atomic-min (values may be negative).
    if (val >= 0.0f) {
        atomicMin((int*)addr, __float_as_int(val));
    } else {
        atomicMax((unsigned int*)addr, __float_as_uint(val));
    }
}

__global__ void init_kernel() {
    int i = blockIdx.x * blockDim.x + threadIdx.x;
    if (i < B_SZ * N_PTS) gMinX[i] = __int_as_float(0x7f800000); // +inf
    if (i < B_SZ * M_PTS) gMinY[i] = __int_as_float(0x7f800000);
    if (i == 0) { gSumX = 0.0f; gSumY = 0.0f; }
}

__global__ __launch_bounds__(BLOCK) void chamfer_kernel(
    const float* __restrict__ pred, const float* __restrict__ target)
{
    // Pair-packed SoA tiles: element k holds {coord_{2k}, coord_{2k+1}}.
    // LDS.64 delivers born-packed f32x2 operands (no packing MOVs in hot loop).
    __shared__ ull sTx[TILE2], sTy[TILE2], sTz[TILE2], sTw[TILE2];  // target tile
    __shared__ ull sPx[TILE2], sPy[TILE2], sPz[TILE2], sPw[TILE2];  // pred tile

    const int b = blockIdx.z;
    const float* __restrict__ predB = pred   + (size_t)b * N_PTS * 3;
    const float* __restrict__ targB = target + (size_t)b * M_PTS * 3;

    const int ownerBase = blockIdx.x * OWNERS;
    const int chunkBase = blockIdx.y * CHUNK;
    const int t = threadIdx.x;

    // Owner coordinates, pre-negated and duplicated into f32x2 pairs.
    ull axx[IPT], ayy[IPT], azz[IPT];   // owned pred points (negated)
    ull cxx[IPT], cyy[IPT], czz[IPT];   // owned target points (negated)
    float mn1[IPT], mn2[IPT];

#pragma unroll
    for (int p = 0; p < IPT; p++) {
        int i = ownerBase + t + p * BLOCK;
        float x = predB[3 * i + 0], y = predB[3 * i + 1], z = predB[3 * i + 2];
        axx[p] = pack2(-x, -x); ayy[p] = pack2(-y, -y); azz[p] = pack2(-z, -z);
        x = targB[3 * i + 0]; y = targB[3 * i + 1]; z = targB[3 * i + 2];
        cxx[p] = pack2(-x, -x); cyy[p] = pack2(-y, -y); czz[p] = pack2(-z, -z);
        mn1[p] = __int_as_float(0x7f800000);
        mn2[p] = __int_as_float(0x7f800000);
    }

    for (int tile = 0; tile < CHUNK; tile += TILE) {
        int j = chunkBase + tile + t;   // t < TILE
        {
            float x = targB[3 * j + 0], y = targB[3 * j + 1], z = targB[3 * j + 2];
            ((float*)sTx)[t] = x;
            ((float*)sTy)[t] = y;
            ((float*)sTz)[t] = z;
            ((float*)sTw)[t] = 0.5f * (x * x + y * y + z * z);
            x = predB[3 * j + 0]; y = predB[3 * j + 1]; z = predB[3 * j + 2];
            ((float*)sPx)[t] = x;
            ((float*)sPy)[t] = y;
            ((float*)sPz)[t] = z;
            ((float*)sPw)[t] = 0.5f * (x * x + y * y + z * z);
        }
        __syncthreads();

#pragma unroll 4
        for (int jj = 0; jj < TILE2; jj++) {
            // direction X: pred owners vs target tile (2 j's per iteration)
            {
                ull tx = sTx[jj], ty = sTy[jj], tz = sTz[jj], tw = sTw[jj];
#pragma unroll
                for (int p = 0; p < IPT; p++) {
                    ull v = fma2(azz[p], tz, tw);
                    v = fma2(ayy[p], ty, v);
                    v = fma2(axx[p], tx, v);
                    float v0, v1;
                    unpack2(v, v0, v1);
                    mn1[p] = fminf(mn1[p], v0);
                    mn1[p] = fminf(mn1[p], v1);
                }
            }
            // direction Y: target owners vs pred tile
            {
                ull qx = sPx[jj], qy = sPy[jj], qz = sPz[jj], qw = sPw[jj];
#pragma unroll
                for (int p = 0; p < IPT; p++) {
                    ull v = fma2(czz[p], qz, qw);
                    v = fma2(cyy[p], qy, v);
                    v = fma2(cxx[p], qx, v);
                    float v0, v1;
                    unpack2(v, v0, v1);
                    mn2[p] = fminf(mn2[p], v0);
                    mn2[p] = fminf(mn2[p], v1);
                }
            }
        }
        __syncthreads();
    }

#pragma unroll
    for (int p = 0; p < IPT; p++) {
        int i = ownerBase + t + p * BLOCK;
        atomicMinFloat(&gMinX[b * N_PTS + i], mn1[p]);
        atomicMinFloat(&gMinY[b * M_PTS + i], mn2[p]);
    }
}

__global__ void reduce_kernel(const float* __restrict__ pred,
                              const float* __restrict__ target)
{
    __shared__ float sx[256 / 32];
    __shared__ float sy[256 / 32];

    int i = blockIdx.x * blockDim.x + threadIdx.x;
    float vx = 0.0f, vy = 0.0f;
    if (i < B_SZ * N_PTS) {
        float x = pred[3 * i + 0], y = pred[3 * i + 1], z = pred[3 * i + 2];
        vx = 2.0f * gMinX[i] + (x * x + y * y + z * z);
    }
    if (i < B_SZ * M_PTS) {
        float x = target[3 * i + 0], y = target[3 * i + 1], z = target[3 * i + 2];
        vy = 2.0f * gMinY[i] + (x * x + y * y + z * z);
    }
    // warp reduce
#pragma unroll
    for (int off = 16; off > 0; off >>= 1) {
        vx += __shfl_down_sync(0xffffffffu, vx, off);
        vy += __shfl_down_sync(0xffffffffu, vy, off);
    }
    int lane = threadIdx.x & 31;
    int warp = threadIdx.x >> 5;
    if (lane == 0) { sx[warp] = vx; sy[warp] = vy; }
    __syncthreads();
    if (warp == 0) {
        vx = (lane < (blockDim.x >> 5)) ? sx[lane] : 0.0f;
        vy = (lane < (blockDim.x >> 5)) ? sy[lane] : 0.0f;
#pragma unroll
        for (int off = 16; off > 0; off >>= 1) {
            vx += __shfl_down_sync(0xffffffffu, vx, off);
            vy += __shfl_down_sync(0xffffffffu, vy, off);
        }
        if (lane == 0) {
            atomicAdd(&gSumX, vx);
            atomicAdd(&gSumY, vy);
        }
    }
}

__global__ void finalize_kernel(const float* __restrict__ bpp,
                                const float* __restrict__ lamda,
                                float* __restrict__ out)
{
    float dist = gSumX * (1.0f / (B_SZ * N_PTS)) + gSumY * (1.0f / (B_SZ * M_PTS));
    out[0] = dist + lamda[0] * bpp[0];
}

extern "C" void kernel_launch(void* const* d_in, const int* in_sizes, int n_in,
                              void* d_out, int out_size)
{
    const float* pred   = (const float*)d_in[0];
    const float* target = (const float*)d_in[1];
    const float* bpp    = (const float*)d_in[2];
    const float* lamda  = (const float*)d_in[3];
    float* out = (float*)d_out;

    // 1) init mins / accumulators
    init_kernel<<<(B_SZ * N_PTS + 255) / 256, 256>>>();

    // 2) fused two-direction chamfer min (f32x2 packed inner loop)
    dim3 grid(N_PTS / OWNERS, S_CHUNKS, B_SZ);  // (8, 16, 4)
    chamfer_kernel<<<grid, BLOCK>>>(pred, target);

    // 3) per-point d2 + sum reduction
    reduce_kernel<<<(B_SZ * N_PTS + 255) / 256, 256>>>(pred, target);

    // 4) scalar finalize
    finalize_kernel<<<1, 1>>>(bpp, lamda, out);
}

// round 4
// speedup vs baseline: 1.6317x; 1.4228x over previous
#include <cuda_runtime.h>
#include <cstdint>

// Problem shape (fixed by the reference setup_inputs)
#define B_SZ   4
#define N_PTS  8192
#define M_PTS  8192

// Chamfer compute tiling
#define BLOCK  128                 // threads per block (4 warps)
#define OWN    8                   // owner pred points per thread
#define TI     (BLOCK * OWN)       // 1024 pred points per block
#define TILE   256                 // target points per block (one shared tile)
#define TILE2  (TILE / 2)          // packed j-pairs
#define IC     (N_PTS / TI)        // 8  i-chunks
#define JC     (M_PTS / TILE)      // 32 j-chunks

#define FINF __int_as_float(0x7f800000)

typedef unsigned long long ull;

__device__ float gMinX[B_SZ * N_PTS];   // min_j 0.5*d^2(i,j)   (row mins)
__device__ float gMinY[B_SZ * M_PTS];   // min_i 0.5*d^2(i,j)   (col mins)
__device__ float gSumX;
__device__ float gSumY;
__device__ int   gCount;

// ---- packed f32x2 helpers ----
__device__ __forceinline__ ull pack2(float lo, float hi) {
    ull r;
    asm("mov.b64 %0, {%1,%2};" : "=l"(r) : "f"(lo), "f"(hi));
    return r;
}
__device__ __forceinline__ ull fma2(ull a, ull b, ull c) {
    ull d;
    asm("fma.rn.f32x2 %0, %1, %2, %3;" : "=l"(d) : "l"(a), "l"(b), "l"(c));
    return d;
}
__device__ __forceinline__ ull add2(ull a, ull b) {
    ull d;
    asm("add.rn.f32x2 %0, %1, %2;" : "=l"(d) : "l"(a), "l"(b));
    return d;
}
__device__ __forceinline__ void unpack2(ull v, float& lo, float& hi) {
    asm("mov.b64 {%0,%1}, %2;" : "=f"(lo), "=f"(hi) : "l"(v));
}

__device__ __forceinline__ void atomicMinFloat(float* addr, float val) {
    if (val >= 0.0f) {
        atomicMin((int*)addr, __float_as_int(val));
    } else {
        atomicMax((unsigned int*)addr, __float_as_uint(val));
    }
}

__global__ void init_kernel() {
    int i = blockIdx.x * blockDim.x + threadIdx.x;
    if (i < B_SZ * N_PTS) gMinX[i] = FINF;
    if (i < B_SZ * M_PTS) gMinY[i] = FINF;
    if (i == 0) { gSumX = 0.0f; gSumY = 0.0f; gCount = 0; }
}

// Each unique pair (i,j) computed exactly ONCE as v = 0.5*d^2(i,j):
//   v = (0.5|t_j|^2 + 0.5|p_i|^2) - p_i . t_j    [1 add2 + 3 fma2, packed over 2 j's]
// Valid objective for BOTH row mins (over j) and col mins (over i).
// Row mins: register accumulators (thread owns 8 pred points).
// Col mins: per-warp shared arrays, lane-rotated jp => lane-exclusive RMW, no atomics.
__global__ __launch_bounds__(BLOCK) void chamfer_kernel(
    const float* __restrict__ pred, const float* __restrict__ target)
{
    // Pair-packed SoA target tile: element k holds coords of {j=2k, j=2k+1}.
    __shared__ ull sTx[TILE2], sTy[TILE2], sTz[TILE2], sTw[TILE2];
    __shared__ ull sCol[BLOCK / 32][TILE2];   // per-warp packed column mins

    const int b = blockIdx.z;
    const float* __restrict__ predB = pred   + (size_t)b * N_PTS * 3;
    const float* __restrict__ targB = target + (size_t)b * M_PTS * 3;

    const int Ibase = blockIdx.x * TI;
    const int Jbase = blockIdx.y * TILE;
    const int t = threadIdx.x;
    const int lane = t & 31;
    const int w = t >> 5;

    // init per-warp colmins to +inf
    ull inf2 = pack2(FINF, FINF);
#pragma unroll
    for (int k = t; k < (BLOCK / 32) * TILE2; k += BLOCK)
        ((ull*)sCol)[k] = inf2;

    // load target tile (x, y, z, 0.5|t|^2), pair-packed SoA
    for (int k = t; k < TILE; k += BLOCK) {
        int j = Jbase + k;
        float x = targB[3 * j + 0], y = targB[3 * j + 1], z = targB[3 * j + 2];
        ((float*)sTx)[k] = x;
        ((float*)sTy)[k] = y;
        ((float*)sTz)[k] = z;
        ((float*)sTw)[k] = 0.5f * (x * x + y * y + z * z);
    }

    // owner pred points: negated coords + half-norm, duplicated into f32x2 pairs
    ull ax[OWN], ay[OWN], az[OWN], hp[OWN];
    float rm[OWN];
#pragma unroll
    for (int p = 0; p < OWN; p++) {
        int i = Ibase + t + p * BLOCK;
        float x = predB[3 * i + 0], y = predB[3 * i + 1], z = predB[3 * i + 2];
        float h = 0.5f * (x * x + y * y + z * z);
        ax[p] = pack2(-x, -x); ay[p] = pack2(-y, -y); az[p] = pack2(-z, -z);
        hp[p] = pack2(h, h);
        rm[p] = FINF;
    }

    __syncthreads();

    ull* scol = sCol[w];

    for (int s = 0; s < TILE2; s++) {
        int jp = (s + lane) & (TILE2 - 1);   // lane-exclusive within warp each step
        ull tx = sTx[jp], ty = sTy[jp], tz = sTz[jp], tw = sTw[jp];
        float c0 = FINF, c1 = FINF;
#pragma unroll
        for (int p = 0; p < OWN; p++) {
            ull v = fma2(az[p], tz, add2(tw, hp[p]));  // 0.5(|p|^2+|t|^2) - pz*tz
            v = fma2(ay[p], ty, v);
            v = fma2(ax[p], tx, v);                     // = 0.5 * d^2
            float v0, v1;
            unpack2(v, v0, v1);
            rm[p] = fminf(rm[p], fminf(v0, v1));        // row min (over j)
            c0 = fminf(c0, v0);                          // col partial (over this thread's i's)
            c1 = fminf(c1, v1);
        }
        // fold into per-warp column min (lane-exclusive jp, no race)
        ull cc = scol[jp];
        float o0, o1;
        unpack2(cc, o0, o1);
        scol[jp] = pack2(fminf(o0, c0), fminf(o1, c1));
    }

    // row mins -> global
#pragma unroll
    for (int p = 0; p < OWN; p++) {
        int i = Ibase + t + p * BLOCK;
        atomicMinFloat(&gMinX[b * N_PTS + i], rm[p]);
    }

    __syncthreads();

    // column mins: combine 4 warps' arrays, one jp per thread (BLOCK == TILE2)
    {
        int jp = t;
        float m0 = FINF, m1 = FINF;
#pragma unroll
        for (int w2 = 0; w2 < BLOCK / 32; w2++) {
            float a, bb;
            unpack2(sCol[w2][jp], a, bb);
            m0 = fminf(m0, a);
            m1 = fminf(m1, bb);
        }
        atomicMinFloat(&gMinY[b * M_PTS + Jbase + 2 * jp + 0], m0);
        atomicMinFloat(&gMinY[b * M_PTS + Jbase + 2 * jp + 1], m1);
    }
}

// sum of d^2 = 2 * min(0.5 d^2), global reduction + (last block) finalize
__global__ void reduce_fin_kernel(const float* __restrict__ bpp,
                                  const float* __restrict__ lamda,
                                  float* __restrict__ out)
{
    __shared__ float sx[256 / 32];
    __shared__ float sy[256 / 32];

    int i = blockIdx.x * blockDim.x + threadIdx.x;
    float vx = 0.0f, vy = 0.0f;
    if (i < B_SZ * N_PTS) vx = 2.0f * gMinX[i];
    if (i < B_SZ * M_PTS) vy = 2.0f * gMinY[i];

#pragma unroll
    for (int off = 16; off > 0; off >>= 1) {
        vx += __shfl_down_sync(0xffffffffu, vx, off);
        vy += __shfl_down_sync(0xffffffffu, vy, off);
    }
    int lane = threadIdx.x & 31;
    int warp = threadIdx.x >> 5;
    if (lane == 0) { sx[warp] = vx; sy[warp] = vy; }
    __syncthreads();
    if (warp == 0) {
        vx = (lane < (blockDim.x >> 5)) ? sx[lane] : 0.0f;
        vy = (lane < (blockDim.x >> 5)) ? sy[lane] : 0.0f;
#pragma unroll
        for (int off = 16; off > 0; off >>= 1) {
            vx += __shfl_down_sync(0xffffffffu, vx, off);
            vy += __shfl_down_sync(0xffffffffu, vy, off);
        }
        if (lane == 0) {
            atomicAdd(&gSumX, vx);
            atomicAdd(&gSumY, vy);
            __threadfence();
            int ticket = atomicAdd(&gCount, 1);
            if (ticket == (int)gridDim.x - 1) {
                float sX = atomicAdd(&gSumX, 0.0f);   // all prior adds visible
                float sY = atomicAdd(&gSumY, 0.0f);
                float dist = sX * (1.0f / (B_SZ * N_PTS)) + sY * (1.0f / (B_SZ * M_PTS));
                out[0] = dist + lamda[0] * bpp[0];
            }
        }
    }
}

extern "C" void kernel_launch(void* const* d_in, const int* in_sizes, int n_in,
                              void* d_out, int out_size)
{
    const float* pred   = (const float*)d_in[0];
    const float* target = (const float*)d_in[1];
    const float* bpp    = (const float*)d_in[2];
    const float* lamda  = (const float*)d_in[3];
    float* out = (float*)d_out;

    // 1) init mins / accumulators / ticket
    init_kernel<<<(B_SZ * N_PTS + 255) / 256, 256>>>();

    // 2) single-pass chamfer: each pair once as 0.5*d^2, row mins in regs,
    //    col mins per-warp shared (lane-rotated, atomic-free)
    dim3 grid(IC, JC, B_SZ);   // (8, 32, 4) = 1024 blocks
    chamfer_kernel<<<grid, BLOCK>>>(pred, target);

    // 3) global sum + fused finalize (last-block ticket)
    reduce_fin_kernel<<<(B_SZ * N_PTS + 255) / 256, 256>>>(bpp, lamda, out);
}

// round 5
// speedup vs baseline: 1.6802x; 1.0297x over previous
#include <cuda_runtime.h>
#include <cstdint>

// Problem shape (fixed by the reference setup_inputs)
#define B_SZ   4
#define N_PTS  8192
#define M_PTS  8192

// Chamfer compute tiling
#define BLOCK  128                 // threads per block (4 warps)
#define OWN    8                   // owner pred points per thread
#define TI     (BLOCK * OWN)       // 1024 pred points per block
#define TILE   256                 // target points per block (one shared tile)
#define TILE2  (TILE / 2)          // packed j-pairs
#define IC     (N_PTS / TI)        // 8  i-chunks
#define JC     (M_PTS / TILE)      // 32 j-chunks

#define FINF __int_as_float(0x7f800000)

typedef unsigned long long ull;

// Non-atomic partial-min arrays: every slot written exactly once by one block.
__device__ float gPartX[JC][B_SZ * N_PTS];   // [jc][b*N+i]: min over j-slice of 0.5*d^2
__device__ float gPartY[IC][B_SZ * M_PTS];   // [ic][b*M+j]: min over i-slice of 0.5*d^2
__device__ float gSumX;
__device__ float gSumY;
__device__ int   gCount;
__device__ int   gEpoch;   // makes sum/ticket reset graph-replay-safe

// ---- packed f32x2 helpers ----
__device__ __forceinline__ ull pack2(float lo, float hi) {
    ull r;
    asm("mov.b64 %0, {%1,%2};" : "=l"(r) : "f"(lo), "f"(hi));
    return r;
}
__device__ __forceinline__ ull fma2(ull a, ull b, ull c) {
    ull d;
    asm("fma.rn.f32x2 %0, %1, %2, %3;" : "=l"(d) : "l"(a), "l"(b), "l"(c));
    return d;
}
__device__ __forceinline__ ull add2(ull a, ull b) {
    ull d;
    asm("add.rn.f32x2 %0, %1, %2;" : "=l"(d) : "l"(a), "l"(b));
    return d;
}
__device__ __forceinline__ void unpack2(ull v, float& lo, float& hi) {
    asm("mov.b64 {%0,%1}, %2;" : "=f"(lo), "=f"(hi) : "l"(v));
}

// Each unique pair (i,j) computed exactly ONCE as v = 0.5*d^2(i,j):
//   v = (0.5|t_j|^2 + 0.5|p_i|^2) - p_i . t_j    [1 add2 + 3 fma2, packed over 2 j's]
// Row mins: register accumulators (thread owns 8 pred points) -> gPartX plain store.
// Col mins: per-warp shared arrays, lane-rotated jp => lane-exclusive RMW -> gPartY.
__global__ __launch_bounds__(BLOCK) void chamfer_kernel(
    const float* __restrict__ pred, const float* __restrict__ target)
{
    // Pair-packed SoA target tile: element k holds coords of {j=2k, j=2k+1}.
    __shared__ ull sTx[TILE2], sTy[TILE2], sTz[TILE2], sTw[TILE2];
    __shared__ ull sCol[BLOCK / 32][TILE2];   // per-warp packed column mins

    const int b = blockIdx.z;
    const float* __restrict__ predB = pred   + (size_t)b * N_PTS * 3;
    const float* __restrict__ targB = target + (size_t)b * M_PTS * 3;

    const int ic = blockIdx.x;
    const int jc = blockIdx.y;
    const int Ibase = ic * TI;
    const int Jbase = jc * TILE;
    const int t = threadIdx.x;
    const int lane = t & 31;
    const int w = t >> 5;

    // init per-warp colmins to +inf
    ull inf2 = pack2(FINF, FINF);
#pragma unroll
    for (int k = t; k < (BLOCK / 32) * TILE2; k += BLOCK)
        ((ull*)sCol)[k] = inf2;

    // load target tile (x, y, z, 0.5|t|^2), pair-packed SoA
    for (int k = t; k < TILE; k += BLOCK) {
        int j = Jbase + k;
        float x = targB[3 * j + 0], y = targB[3 * j + 1], z = targB[3 * j + 2];
        ((float*)sTx)[k] = x;
        ((float*)sTy)[k] = y;
        ((float*)sTz)[k] = z;
        ((float*)sTw)[k] = 0.5f * (x * x + y * y + z * z);
    }

    // owner pred points: negated coords + half-norm, duplicated into f32x2 pairs
    ull ax[OWN], ay[OWN], az[OWN], hp[OWN];
    float rm[OWN];
#pragma unroll
    for (int p = 0; p < OWN; p++) {
        int i = Ibase + t + p * BLOCK;
        float x = predB[3 * i + 0], y = predB[3 * i + 1], z = predB[3 * i + 2];
        float h = 0.5f * (x * x + y * y + z * z);
        ax[p] = pack2(-x, -x); ay[p] = pack2(-y, -y); az[p] = pack2(-z, -z);
        hp[p] = pack2(h, h);
        rm[p] = FINF;
    }

    __syncthreads();

    ull* scol = sCol[w];

    for (int s = 0; s < TILE2; s++) {
        int jp = (s + lane) & (TILE2 - 1);   // lane-exclusive within warp each step
        ull tx = sTx[jp], ty = sTy[jp], tz = sTz[jp], tw = sTw[jp];
        float c0 = FINF, c1 = FINF;
#pragma unroll
        for (int p = 0; p < OWN; p++) {
            ull v = fma2(az[p], tz, add2(tw, hp[p]));  // 0.5(|p|^2+|t|^2) - pz*tz
            v = fma2(ay[p], ty, v);
            v = fma2(ax[p], tx, v);                     // = 0.5 * d^2
            float v0, v1;
            unpack2(v, v0, v1);
            rm[p] = fminf(rm[p], fminf(v0, v1));        // row min (over j)
            c0 = fminf(c0, v0);                          // col partial (over this thread's i's)
            c1 = fminf(c1, v1);
        }
        // fold into per-warp column min (lane-exclusive jp, no race)
        ull cc = scol[jp];
        float o0, o1;
        unpack2(cc, o0, o1);
        scol[jp] = pack2(fminf(o0, c0), fminf(o1, c1));
    }

    // row partial mins -> dedicated slice (plain store, no atomics)
    float* __restrict__ px = &gPartX[jc][b * N_PTS];
#pragma unroll
    for (int p = 0; p < OWN; p++)
        px[Ibase + t + p * BLOCK] = rm[p];

    __syncthreads();

    // column mins: combine 4 warps' arrays, one jp per thread (BLOCK == TILE2)
    {
        int jp = t;
        float m0 = FINF, m1 = FINF;
#pragma unroll
        for (int w2 = 0; w2 < BLOCK / 32; w2++) {
            float a, bb;
            unpack2(sCol[w2][jp], a, bb);
            m0 = fminf(m0, a);
            m1 = fminf(m1, bb);
        }
        float* __restrict__ py = &gPartY[ic][b * M_PTS + Jbase];
        py[2 * jp + 0] = m0;
        py[2 * jp + 1] = m1;
    }
}

// min over partial slices, global sum, (last block) finalize
__global__ __launch_bounds__(256) void reduce_fin_kernel(
    const float* __restrict__ bpp, const float* __restrict__ lamda,
    float* __restrict__ out)
{
    __shared__ float sx[256 / 32];
    __shared__ float sy[256 / 32];

    const int i = blockIdx.x * blockDim.x + threadIdx.x;   // covers B*N == B*M

    float mx = FINF;
#pragma unroll
    for (int jc = 0; jc < JC; jc++)
        mx = fminf(mx, gPartX[jc][i]);
    float my = FINF;
#pragma unroll
    for (int ic = 0; ic < IC; ic++)
        my = fminf(my, gPartY[ic][i]);

    float vx = 2.0f * mx;   // d^2 = 2 * (0.5 d^2)
    float vy = 2.0f * my;

#pragma unroll
    for (int off = 16; off > 0; off >>= 1) {
        vx += __shfl_down_sync(0xffffffffu, vx, off);
        vy += __shfl_down_sync(0xffffffffu, vy, off);
    }
    int lane = threadIdx.x & 31;
    int warp = threadIdx.x >> 5;
    if (lane == 0) { sx[warp] = vx; sy[warp] = vy; }
    __syncthreads();
    if (warp == 0) {
        vx = (lane < (blockDim.x >> 5)) ? sx[lane] : 0.0f;
        vy = (lane < (blockDim.x >> 5)) ? sy[lane] : 0.0f;
#pragma unroll
        for (int off = 16; off > 0; off >>= 1) {
            vx += __shfl_down_sync(0xffffffffu, vx, off);
            vy += __shfl_down_sync(0xffffffffu, vy, off);
        }
        if (lane == 0) {
            atomicAdd(&gSumX, vx);
            atomicAdd(&gSumY, vy);
            __threadfence();
            int ticket = atomicAdd(&gCount, 1);
            if (ticket == (int)gridDim.x - 1) {
                float sX = atomicAdd(&gSumX, 0.0f);   // all prior adds visible
                float sY = atomicAdd(&gSumY, 0.0f);
                float dist = sX * (1.0f / (B_SZ * N_PTS)) + sY * (1.0f / (B_SZ * M_PTS));
                out[0] = dist + lamda[0] * bpp[0];
                // reset accumulators for the next graph replay
                gSumX = 0.0f;
                gSumY = 0.0f;
                __threadfence();
                gCount = 0;
            }
        }
    }
}

extern "C" void kernel_launch(void* const* d_in, const int* in_sizes, int n_in,
                              void* d_out, int out_size)
{
    const float* pred   = (const float*)d_in[0];
    const float* target = (const float*)d_in[1];
    const float* bpp    = (const float*)d_in[2];
    const float* lamda  = (const float*)d_in[3];
    float* out = (float*)d_out;

    // 1) single-pass chamfer: each pair once as 0.5*d^2; partial mins to
    //    dedicated slices (no init kernel, no global atomics)
    dim3 grid(IC, JC, B_SZ);   // (8, 32, 4) = 1024 blocks
    chamfer_kernel<<<grid, BLOCK>>>(pred, target);

    // 2) slice-min + global sum + fused finalize (last-block ticket, self-resetting)
    reduce_fin_kernel<<<(B_SZ * N_PTS) / 256, 256>>>(bpp, lamda, out);
}